// round 17
// baseline (speedup 1.0000x reference)
#include <cuda_runtime.h>
#include <math.h>

#define NUM_TASKS 1000
#define NF 256
#define NH 128
#define BATCH 4096
#define XPITCH 12   // transposed-x row pitch (floats): 48B, 16B-aligned float4 reads
#define PF 8        // explicit LDG.128 prefetch depth per warp

__device__ int g_off[NUM_TASKS + 1];
__device__ int g_order[BATCH];

// ---------------------------------------------------------------------------
// Fused prep: count + scan + scatter, ONE single-block kernel.
// ---------------------------------------------------------------------------
__global__ __launch_bounds__(1024) void prep_k(const int* __restrict__ task_ids, int n) {
    __shared__ int cnt[NUM_TASKS];
    __shared__ int sc[1024];
    int tid = threadIdx.x;

    for (int i = tid; i < NUM_TASKS; i += 1024) cnt[i] = 0;
    __syncthreads();
    for (int i = tid; i < n; i += 1024) atomicAdd(&cnt[task_ids[i]], 1);
    __syncthreads();

    sc[tid] = (tid < NUM_TASKS) ? cnt[tid] : 0;
    __syncthreads();
    for (int d = 1; d < 1024; d <<= 1) {
        int v = (tid >= d) ? sc[tid - d] : 0;
        __syncthreads();
        sc[tid] += v;
        __syncthreads();
    }
    if (tid < NUM_TASKS) {
        g_off[tid + 1] = sc[tid];
        if (tid == 0) g_off[0] = 0;
        cnt[tid] = (tid == 0) ? 0 : sc[tid - 1];
    }
    __syncthreads();

    for (int i = tid; i < n; i += 1024) {
        int p = atomicAdd(&cnt[task_ids[i]], 1);
        g_order[p] = i;
    }
}

__device__ __forceinline__ float gelu_exact(float h) {
    return 0.5f * h * (1.0f + erff(h * 0.70710678118654752f));
}

// ---------------------------------------------------------------------------
// Chunk body. 8 warp-groups; wg streams its 32 contiguous W rows via LDG.128
// through an explicit 8-deep register prefetch ring (guaranteed 8 loads in
// flight per warp). x read from transposed smem (LDS.128 broadcasts).
// Pad slots (s >= S) replicate sample 0; computed but never stored.
// ---------------------------------------------------------------------------
template<int SS>
__device__ __forceinline__ void do_chunk(
    int base, int S, int tid, int wg, int lane, int j,
    const float* __restrict__ x, const float* __restrict__ W,
    float b1, float w2, float b2,
    float* __restrict__ swxt, float (*hpart)[8][NH], int* sidx, float (*sred)[8],
    float* __restrict__ out)
{
    // Stage x transposed: swxt[f*XPITCH + s]; f = tid (coalesced LDG per sample)
    #pragma unroll
    for (int s = 0; s < SS; s++) {
        int src = base + ((s < S) ? s : 0);
        int ord = __ldg(&g_order[src]);
        if (tid == s) sidx[s] = ord;
        swxt[tid * XPITCH + s] = __ldg(&x[(size_t)ord * NF + tid]);
    }
    __syncthreads();

    const float4* __restrict__ Wv =
        (const float4*)(W + (size_t)(wg * 32) * NH) + lane;   // row stride 32 float4

    float4 acc[SS];
    #pragma unroll
    for (int s = 0; s < SS; s++) acc[s] = make_float4(0.f, 0.f, 0.f, 0.f);

    // Prefetch ring: 8 LDG.128 always outstanding
    float4 wbuf[PF];
    #pragma unroll
    for (int i = 0; i < PF; i++) wbuf[i] = __ldg(&Wv[i * 32]);

    #pragma unroll
    for (int r = 0; r < 32; r++) {
        float4 wv = wbuf[r & (PF - 1)];
        if (r < 32 - PF) wbuf[r & (PF - 1)] = __ldg(&Wv[(r + PF) * 32]);

        const float4* xp = (const float4*)&swxt[(wg * 32 + r) * XPITCH];
        float4 xa = xp[0];                                    // samples 0..3 (broadcast)
        acc[0].x = fmaf(xa.x, wv.x, acc[0].x); acc[0].y = fmaf(xa.x, wv.y, acc[0].y);
        acc[0].z = fmaf(xa.x, wv.z, acc[0].z); acc[0].w = fmaf(xa.x, wv.w, acc[0].w);
        acc[1].x = fmaf(xa.y, wv.x, acc[1].x); acc[1].y = fmaf(xa.y, wv.y, acc[1].y);
        acc[1].z = fmaf(xa.y, wv.z, acc[1].z); acc[1].w = fmaf(xa.y, wv.w, acc[1].w);
        acc[2].x = fmaf(xa.z, wv.x, acc[2].x); acc[2].y = fmaf(xa.z, wv.y, acc[2].y);
        acc[2].z = fmaf(xa.z, wv.z, acc[2].z); acc[2].w = fmaf(xa.z, wv.w, acc[2].w);
        acc[3].x = fmaf(xa.w, wv.x, acc[3].x); acc[3].y = fmaf(xa.w, wv.y, acc[3].y);
        acc[3].z = fmaf(xa.w, wv.z, acc[3].z); acc[3].w = fmaf(xa.w, wv.w, acc[3].w);
        if (SS == 8) {
            float4 xb = xp[1];                                // samples 4..7
            acc[4].x = fmaf(xb.x, wv.x, acc[4].x); acc[4].y = fmaf(xb.x, wv.y, acc[4].y);
            acc[4].z = fmaf(xb.x, wv.z, acc[4].z); acc[4].w = fmaf(xb.x, wv.w, acc[4].w);
            acc[5].x = fmaf(xb.y, wv.x, acc[5].x); acc[5].y = fmaf(xb.y, wv.y, acc[5].y);
            acc[5].z = fmaf(xb.y, wv.z, acc[5].z); acc[5].w = fmaf(xb.y, wv.w, acc[5].w);
            acc[6].x = fmaf(xb.z, wv.x, acc[6].x); acc[6].y = fmaf(xb.z, wv.y, acc[6].y);
            acc[6].z = fmaf(xb.z, wv.z, acc[6].z); acc[6].w = fmaf(xb.z, wv.w, acc[6].w);
            acc[7].x = fmaf(xb.w, wv.x, acc[7].x); acc[7].y = fmaf(xb.w, wv.y, acc[7].y);
            acc[7].z = fmaf(xb.w, wv.z, acc[7].z); acc[7].w = fmaf(xb.w, wv.w, acc[7].w);
        }
    }

    #pragma unroll
    for (int s = 0; s < SS; s++)
        *(float4*)&hpart[wg][s][lane * 4] = acc[s];
    __syncthreads();

    if (tid < NH) {
        int l2l = tid & 31, l2w = tid >> 5;
        #pragma unroll
        for (int s = 0; s < SS; s++) {
            float h = b1;
            #pragma unroll
            for (int g = 0; g < 8; g++) h += hpart[g][s][j];
            float v = gelu_exact(h) * w2;
            v += __shfl_xor_sync(0xffffffffu, v, 16);
            v += __shfl_xor_sync(0xffffffffu, v, 8);
            v += __shfl_xor_sync(0xffffffffu, v, 4);
            v += __shfl_xor_sync(0xffffffffu, v, 2);
            v += __shfl_xor_sync(0xffffffffu, v, 1);
            if (l2l == 0) sred[l2w][s] = v;
        }
    }
    __syncthreads();

    if (tid < S) {
        float sum = sred[0][tid] + sred[1][tid] + sred[2][tid] + sred[3][tid];
        out[sidx[tid]] = sum + b2;
    }
    __syncthreads();
}

// One CTA per task, 256 threads, 2 CTAs/SM (128-reg budget).
__global__ __launch_bounds__(256, 2) void mlp_k(
    const float* __restrict__ x,
    const float* __restrict__ l1_emb,
    const float* __restrict__ l1_bias,
    const float* __restrict__ l2_emb,
    const float* __restrict__ l2_bias,
    float* __restrict__ out)
{
    int t = blockIdx.x;
    int beg = g_off[t];
    int n   = g_off[t + 1] - beg;
    if (n == 0) return;

    int tid  = threadIdx.x;
    int wg   = tid >> 5;
    int lane = tid & 31;
    int j    = tid & 127;

    const float* __restrict__ W = l1_emb + (size_t)t * (NF * NH);
    float b1 = l1_bias[t * NH + j];
    float w2 = l2_emb[t * NH + j];
    float b2 = __ldg(&l2_bias[t]);

    __shared__ float swxt[NF * XPITCH];       // 12 KB transposed x
    __shared__ float hpart[8][8][NH];         // 32 KB
    __shared__ int   sidx[8];
    __shared__ float sred[4][8];

    int pos = beg, rem = n;
    while (rem > 0) {
        if (rem > 4) {
            do_chunk<8>(pos, min(rem, 8), tid, wg, lane, j, x, W, b1, w2, b2,
                        swxt, hpart, sidx, sred, out);
            pos += 8; rem -= 8;
        } else {
            do_chunk<4>(pos, rem, tid, wg, lane, j, x, W, b1, w2, b2,
                        swxt, hpart, sidx, sred, out);
            rem = 0;
        }
    }
}

extern "C" void kernel_launch(void* const* d_in, const int* in_sizes, int n_in,
                              void* d_out, int out_size) {
    const float* x       = (const float*)d_in[0];
    const int*   task_id = (const int*)  d_in[1];
    const float* l1_emb  = (const float*)d_in[2];
    const float* l1_bias = (const float*)d_in[3];
    const float* l2_emb  = (const float*)d_in[4];
    const float* l2_bias = (const float*)d_in[5];
    float* out = (float*)d_out;

    int nb = in_sizes[1];  // BATCH

    prep_k<<<1, 1024>>>(task_id, nb);
    mlp_k<<<NUM_TASKS, 256>>>(x, l1_emb, l1_bias, l2_emb, l2_bias, out);
}